// round 7
// baseline (speedup 1.0000x reference)
#include <cuda_runtime.h>
#include <cuda_bf16.h>

// B=16, C=3, H=256, w=5 -> 246x246 pixels x 120 shifts.
// Symmetry: pairT(a,a+d) identical for (a,d) and (a+d,-d)  =>  compute only the
// 60 half-space shifts D+ over interior centers (sum M), then
//   F = 2*M + P - N
// Corrections (P, N: ~2% of terms) run as 1920 small blocks scheduled FIRST so
// their memory latency hides under the main tile waves (R6 had them last ->
// ~30us serial tail). Deterministic: fixed enumeration + fixed-order finalize.
#define HH    256
#define WW    5
#define OUTD  246
#define TX    32
#define TYT   32
#define KP    8
#define NT    128
#define HX    (TX + 2*WW)    // 42
#define HROWS 37
#define NB    16
#define NMAIN (8*8*NB)       // 1024
#define NCORRB (NB*60*2)     // 1920 (NEG/POS split)
#define NTOT  (NMAIN+NCORRB) // 2944

typedef unsigned long long u64;

__device__ float g_partials[NMAIN];
__device__ float g_corr[NCORRB];
__device__ int   g_done = 0;

__device__ __forceinline__ u64 f2_add(u64 a, u64 b) {
    u64 r;
    asm("add.rn.f32x2 %0, %1, %2;" : "=l"(r) : "l"(a), "l"(b));
    return r;
}

__device__ __forceinline__ float pair_term(const float* __restrict__ oB,
                                           const float* __restrict__ sB,
                                           int rA, int cA, int rB, int cB) {
    float sO = 0.f, sS = 0.f;
    #pragma unroll
    for (int c = 0; c < 3; ++c) {
        int offA = c * HH * HH + rA * HH + cA;
        int offB = c * HH * HH + rB * HH + cB;
        sO += fabsf(__ldg(oB + offA) - __ldg(oB + offB));
        sS += fabsf(__ldg(sB + offA) - __ldg(sB + offB));
    }
    return fabsf(sO - sS);
}

__global__ __launch_bounds__(NT, 5)
void contrast_loss_kernel(const float* __restrict__ gO,
                          const float* __restrict__ gS,
                          float* __restrict__ out) {
    __shared__ u64   sh[3][HROWS * HX];
    __shared__ float red[NT / 32];
    __shared__ int   last_flag;

    const int tid  = threadIdx.x;
    const int blin = blockIdx.x;
    const int px   = tid & 31;
    const int ty   = tid >> 5;

    const u64 SGN  = 0x8000000080000000ULL;
    const u64 ABSM = 0x7fffffff7fffffffULL;

    if (blin < NCORRB) {
        // ============== correction path, scheduled FIRST ==============
        const int b   = blin / 120;
        const int rem = blin - b * 120;
        const int s   = rem >> 1;
        const int neg = rem & 1;        // 1 -> N (subtract), 0 -> P (add)
        int i, j;
        if (s < 55) { i = 1 + s / 11; j = (s % 11) - 5; }
        else        { i = 0; j = s - 54; }
        const int aj = (j < 0) ? -j : j;
        // exact floor(t/aj) for aj in [1,5], t <= ~1205
        const unsigned magic = (aj > 0) ? (65536u / (unsigned)aj + 1u) : 0u;

        const float* oB = gO + (size_t)b * 3 * HH * HH;
        const float* sB = gS + (size_t)b * 3 * HH * HH;

        const int n1 = i * OUTD;
        const int n2 = (OUTD - i) * aj;
        const int n  = n1 + n2;

        float total = 0.f;
        for (int idx = tid; idx < n; idx += NT) {
            int ay, ax, by, bx;
            if (neg) {
                // N: a interior, a+d outside interior
                int oy, ox;
                if (idx < n1) { oy = OUTD - i + idx / OUTD; ox = idx - (oy - (OUTD - i)) * OUTD; }
                else {
                    unsigned t = (unsigned)(idx - n1);
                    oy = (int)((t * magic) >> 16);
                    int xo = (int)t - oy * aj;
                    ox = (j > 0) ? (OUTD - j + xo) : xo;
                }
                ay = WW + oy;  ax = WW + ox;
                by = ay + i;   bx = ax + j;
            } else {
                // P: b interior, b-d outside interior; pair (b-d, b)
                int oy, ox;
                if (idx < n1) { oy = idx / OUTD; ox = idx - oy * OUTD; }
                else {
                    unsigned t = (unsigned)(idx - n1);
                    int q = (int)((t * magic) >> 16);
                    int xo = (int)t - q * aj;
                    oy = i + q;
                    ox = (j > 0) ? xo : (OUTD - aj + xo);
                }
                by = WW + oy;  bx = WW + ox;
                ay = by - i;   ax = bx - j;
            }
            total += pair_term(oB, sB, ay, ax, by, bx);
        }
        if (neg) total = -total;

        #pragma unroll
        for (int o = 16; o > 0; o >>= 1)
            total += __shfl_xor_sync(0xffffffffu, total, o);
        if (px == 0) red[ty] = total;
        __syncthreads();
        if (tid == 0)
            g_corr[blin] = red[0] + red[1] + red[2] + red[3];
    } else {
        // ================= main tile path (half-space shifts) =================
        const int ml  = blin - NCORRB;
        const int b   = ml >> 6;
        const int by0 = ((ml >> 3) & 7) * TYT;
        const int bx0 = (ml & 7) * TX;

        const float* oB = gO + (size_t)b * 3 * HH * HH;
        const float* sB = gS + (size_t)b * 3 * HH * HH;
        for (int idx = tid; idx < 3 * HROWS * HX; idx += NT) {
            int c   = idx / (HROWS * HX);
            int rm  = idx - c * (HROWS * HX);
            int r   = rm / HX;
            int col = rm - r * HX;
            int iy = WW + by0 + r, ix = bx0 + col;
            float vo = 0.f, vs = 0.f;
            if (iy < HH && ix < HH) {
                int off = (c * HH + iy) * HH + ix;
                vo = oB[off];
                vs = sB[off];
            }
            sh[c][rm] = (u64)__float_as_uint(vo)
                      | ((u64)__float_as_uint(vs) << 32);
        }
        __syncthreads();

        const int ry0 = ty * KP;

        u64 nc0[KP], nc1[KP], nc2[KP];
        #pragma unroll
        for (int p = 0; p < KP; ++p) {
            int ci = (ry0 + p) * HX + (px + WW);
            nc0[p] = sh[0][ci] ^ SGN;
            nc1[p] = sh[1][ci] ^ SGN;
            nc2[p] = sh[2][ci] ^ SGN;
        }
        float acc[KP];
        #pragma unroll
        for (int p = 0; p < KP; ++p) acc[p] = 0.f;

        // ---- loop A: dx in [-5,0], dy in [1,5] ----
        for (int dx = -5; dx <= 0; ++dx) {
            const int base = ry0 * HX + (px + WW + dx);
            #pragma unroll
            for (int rr = 1; rr <= 12; ++rr) {
                const u64 v0 = sh[0][base + rr * HX];
                const u64 v1 = sh[1][base + rr * HX];
                const u64 v2 = sh[2][base + rr * HX];
                #pragma unroll
                for (int p = 0; p < KP; ++p) {
                    const int dy = rr - p;
                    if (dy >= 1 && dy <= 5) {
                        u64 t0 = f2_add(nc0[p], v0) & ABSM;
                        u64 t1 = f2_add(nc1[p], v1) & ABSM;
                        u64 t2 = f2_add(nc2[p], v2) & ABSM;
                        u64 sm = f2_add(f2_add(t0, t1), t2);
                        float sO = __uint_as_float((unsigned)sm);
                        float sS = __uint_as_float((unsigned)(sm >> 32));
                        acc[p] += fabsf(sO - sS);
                    }
                }
            }
        }
        // ---- loop B: dx in [1,5], dy in [0,5] ----
        for (int dx = 1; dx <= 5; ++dx) {
            const int base = ry0 * HX + (px + WW + dx);
            #pragma unroll
            for (int rr = 0; rr <= 12; ++rr) {
                const u64 v0 = sh[0][base + rr * HX];
                const u64 v1 = sh[1][base + rr * HX];
                const u64 v2 = sh[2][base + rr * HX];
                #pragma unroll
                for (int p = 0; p < KP; ++p) {
                    const int dy = rr - p;
                    if (dy >= 0 && dy <= 5) {
                        u64 t0 = f2_add(nc0[p], v0) & ABSM;
                        u64 t1 = f2_add(nc1[p], v1) & ABSM;
                        u64 t2 = f2_add(nc2[p], v2) & ABSM;
                        u64 sm = f2_add(f2_add(t0, t1), t2);
                        float sO = __uint_as_float((unsigned)sm);
                        float sS = __uint_as_float((unsigned)(sm >> 32));
                        acc[p] += fabsf(sO - sS);
                    }
                }
            }
        }

        float total = 0.f;
        const bool colok = (bx0 + px) < OUTD;
        #pragma unroll
        for (int p = 0; p < KP; ++p)
            if (colok && (by0 + ry0 + p) < OUTD) total += acc[p];

        #pragma unroll
        for (int o = 16; o > 0; o >>= 1)
            total += __shfl_xor_sync(0xffffffffu, total, o);
        if (px == 0) red[ty] = total;
        __syncthreads();
        if (tid == 0)
            g_partials[ml] = red[0] + red[1] + red[2] + red[3];
    }

    // ================= common epilogue: last block finalizes =================
    if (tid == 0) {
        __threadfence();
        int v = atomicAdd(&g_done, 1);
        last_flag = (v == NTOT - 1);
    }
    __syncthreads();

    if (last_flag) {
        __threadfence();
        float s = 0.f;
        for (int k = tid; k < NMAIN; k += NT) s += 2.0f * __ldcg(&g_partials[k]);
        for (int k = tid; k < NCORRB; k += NT) s += __ldcg(&g_corr[k]);
        #pragma unroll
        for (int o = 16; o > 0; o >>= 1)
            s += __shfl_xor_sync(0xffffffffu, s, o);
        if (px == 0) red[ty] = s;
        __syncthreads();
        if (tid == 0) {
            // mean over 16 * 246 * 246 * 120 = 116,190,720 entries
            out[0] = (red[0] + red[1] + red[2] + red[3]) * (1.0f / 116190720.0f);
            g_done = 0;   // reset for graph replay
        }
    }
}

extern "C" void kernel_launch(void* const* d_in, const int* in_sizes, int n_in,
                              void* d_out, int out_size) {
    const float* orig = (const float*)d_in[0];
    const float* sim  = (const float*)d_in[1];
    float* out = (float*)d_out;

    contrast_loss_kernel<<<NTOT, NT>>>(orig, sim, out);
}

// round 8
// speedup vs baseline: 1.0883x; 1.0883x over previous
#include <cuda_runtime.h>
#include <cuda_bf16.h>

// B=16, C=3, H=256, w=5 -> 246x246 pixels x 120 shifts.
// F = 2*M + P - N  (half-space shift symmetry; corrections ~2% of terms).
// R8: occupancy swing — 256 thr x KP=4 (was 128 x KP=8), launch_bounds(256,4)
// caps regs at 64 -> 32 warps/SM (50% occ) to hide LDS latency that bounded R6/R7.
#define HH    256
#define WW    5
#define OUTD  246
#define TX    32
#define TYT   32
#define KP    4
#define NT    256            // 32 x 8 threads
#define HX    (TX + 2*WW)    // 42
#define HROWS 37
#define NB    16
#define NMAIN (8*8*NB)       // 1024
#define NCORRB (NB*60*2)     // 1920 (NEG/POS split)
#define NTOT  (NMAIN+NCORRB) // 2944

typedef unsigned long long u64;

__device__ float g_partials[NMAIN];
__device__ float g_corr[NCORRB];
__device__ int   g_done = 0;

__device__ __forceinline__ u64 f2_add(u64 a, u64 b) {
    u64 r;
    asm("add.rn.f32x2 %0, %1, %2;" : "=l"(r) : "l"(a), "l"(b));
    return r;
}

__device__ __forceinline__ float pair_term(const float* __restrict__ oB,
                                           const float* __restrict__ sB,
                                           int rA, int cA, int rB, int cB) {
    float sO = 0.f, sS = 0.f;
    #pragma unroll
    for (int c = 0; c < 3; ++c) {
        int offA = c * HH * HH + rA * HH + cA;
        int offB = c * HH * HH + rB * HH + cB;
        sO += fabsf(__ldg(oB + offA) - __ldg(oB + offB));
        sS += fabsf(__ldg(sB + offA) - __ldg(sB + offB));
    }
    return fabsf(sO - sS);
}

__global__ __launch_bounds__(NT, 4)
void contrast_loss_kernel(const float* __restrict__ gO,
                          const float* __restrict__ gS,
                          float* __restrict__ out) {
    __shared__ u64   sh[3][HROWS * HX];
    __shared__ float red[NT / 32];
    __shared__ int   last_flag;

    const int tid  = threadIdx.x;
    const int blin = blockIdx.x;
    const int px   = tid & 31;
    const int ty   = tid >> 5;          // 0..7

    const u64 SGN  = 0x8000000080000000ULL;
    const u64 ABSM = 0x7fffffff7fffffffULL;

    if (blin < NMAIN) {
        // ================= main tile path (half-space shifts) =================
        const int b   = blin >> 6;
        const int by0 = ((blin >> 3) & 7) * TYT;
        const int bx0 = (blin & 7) * TX;

        const float* oB = gO + (size_t)b * 3 * HH * HH;
        const float* sB = gS + (size_t)b * 3 * HH * HH;
        // smem row r = image row (WW+by0+r); smem col c = image col (bx0+c)
        for (int idx = tid; idx < 3 * HROWS * HX; idx += NT) {
            int c   = idx / (HROWS * HX);
            int rm  = idx - c * (HROWS * HX);
            int r   = rm / HX;
            int col = rm - r * HX;
            int iy = WW + by0 + r, ix = bx0 + col;
            float vo = 0.f, vs = 0.f;
            if (iy < HH && ix < HH) {
                int off = (c * HH + iy) * HH + ix;
                vo = oB[off];
                vs = sB[off];
            }
            sh[c][rm] = (u64)__float_as_uint(vo)
                      | ((u64)__float_as_uint(vs) << 32);
        }
        __syncthreads();

        const int ry0 = ty * KP;        // 0,4,...,28

        u64 nc0[KP], nc1[KP], nc2[KP];
        #pragma unroll
        for (int p = 0; p < KP; ++p) {
            int ci = (ry0 + p) * HX + (px + WW);
            nc0[p] = sh[0][ci] ^ SGN;
            nc1[p] = sh[1][ci] ^ SGN;
            nc2[p] = sh[2][ci] ^ SGN;
        }
        float acc[KP];
        #pragma unroll
        for (int p = 0; p < KP; ++p) acc[p] = 0.f;

        // ---- loop A: dx in [-5,0], dy in [1,5] ----
        for (int dx = -5; dx <= 0; ++dx) {
            const int base = ry0 * HX + (px + WW + dx);
            #pragma unroll
            for (int rr = 1; rr <= KP + 4; ++rr) {
                const u64 v0 = sh[0][base + rr * HX];
                const u64 v1 = sh[1][base + rr * HX];
                const u64 v2 = sh[2][base + rr * HX];
                #pragma unroll
                for (int p = 0; p < KP; ++p) {
                    const int dy = rr - p;
                    if (dy >= 1 && dy <= 5) {
                        u64 t0 = f2_add(nc0[p], v0) & ABSM;
                        u64 t1 = f2_add(nc1[p], v1) & ABSM;
                        u64 t2 = f2_add(nc2[p], v2) & ABSM;
                        u64 sm = f2_add(f2_add(t0, t1), t2);
                        float sO = __uint_as_float((unsigned)sm);
                        float sS = __uint_as_float((unsigned)(sm >> 32));
                        acc[p] += fabsf(sO - sS);
                    }
                }
            }
        }
        // ---- loop B: dx in [1,5], dy in [0,5] ----
        for (int dx = 1; dx <= 5; ++dx) {
            const int base = ry0 * HX + (px + WW + dx);
            #pragma unroll
            for (int rr = 0; rr <= KP + 4; ++rr) {
                const u64 v0 = sh[0][base + rr * HX];
                const u64 v1 = sh[1][base + rr * HX];
                const u64 v2 = sh[2][base + rr * HX];
                #pragma unroll
                for (int p = 0; p < KP; ++p) {
                    const int dy = rr - p;
                    if (dy >= 0 && dy <= 5) {
                        u64 t0 = f2_add(nc0[p], v0) & ABSM;
                        u64 t1 = f2_add(nc1[p], v1) & ABSM;
                        u64 t2 = f2_add(nc2[p], v2) & ABSM;
                        u64 sm = f2_add(f2_add(t0, t1), t2);
                        float sO = __uint_as_float((unsigned)sm);
                        float sS = __uint_as_float((unsigned)(sm >> 32));
                        acc[p] += fabsf(sO - sS);
                    }
                }
            }
        }

        float total = 0.f;
        const bool colok = (bx0 + px) < OUTD;
        #pragma unroll
        for (int p = 0; p < KP; ++p)
            if (colok && (by0 + ry0 + p) < OUTD) total += acc[p];

        #pragma unroll
        for (int o = 16; o > 0; o >>= 1)
            total += __shfl_xor_sync(0xffffffffu, total, o);
        if (px == 0) red[ty] = total;
        __syncthreads();
        if (tid == 0) {
            float s = 0.f;
            #pragma unroll
            for (int i = 0; i < NT / 32; ++i) s += red[i];
            g_partials[blin] = s;
        }
    } else {
        // ============== correction path (P - N strips), scheduled last ========
        const int cid = blin - NMAIN;
        const int b   = cid / 120;
        const int rem = cid - b * 120;
        const int s   = rem >> 1;
        const int neg = rem & 1;        // 1 -> N (subtract), 0 -> P (add)
        int i, j;
        if (s < 55) { i = 1 + s / 11; j = (s % 11) - 5; }
        else        { i = 0; j = s - 54; }
        const int aj = (j < 0) ? -j : j;
        // exact floor(t/aj) for aj in [1,5], t <= ~1205
        const unsigned magic = (aj > 0) ? (65536u / (unsigned)aj + 1u) : 0u;

        const float* oB = gO + (size_t)b * 3 * HH * HH;
        const float* sB = gS + (size_t)b * 3 * HH * HH;

        const int n1 = i * OUTD;
        const int n2 = (OUTD - i) * aj;
        const int n  = n1 + n2;

        float total = 0.f;
        for (int idx = tid; idx < n; idx += NT) {
            int ay, ax, by, bx;
            if (neg) {
                // N: a interior, a+d outside interior
                int oy, ox;
                if (idx < n1) { oy = OUTD - i + idx / OUTD; ox = idx - (oy - (OUTD - i)) * OUTD; }
                else {
                    unsigned t = (unsigned)(idx - n1);
                    oy = (int)((t * magic) >> 16);
                    int xo = (int)t - oy * aj;
                    ox = (j > 0) ? (OUTD - j + xo) : xo;
                }
                ay = WW + oy;  ax = WW + ox;
                by = ay + i;   bx = ax + j;
            } else {
                // P: b interior, b-d outside interior; pair (b-d, b)
                int oy, ox;
                if (idx < n1) { oy = idx / OUTD; ox = idx - oy * OUTD; }
                else {
                    unsigned t = (unsigned)(idx - n1);
                    int q = (int)((t * magic) >> 16);
                    int xo = (int)t - q * aj;
                    oy = i + q;
                    ox = (j > 0) ? xo : (OUTD - aj + xo);
                }
                by = WW + oy;  bx = WW + ox;
                ay = by - i;   ax = bx - j;
            }
            total += pair_term(oB, sB, ay, ax, by, bx);
        }
        if (neg) total = -total;

        #pragma unroll
        for (int o = 16; o > 0; o >>= 1)
            total += __shfl_xor_sync(0xffffffffu, total, o);
        if (px == 0) red[ty] = total;
        __syncthreads();
        if (tid == 0) {
            float s2 = 0.f;
            #pragma unroll
            for (int i2 = 0; i2 < NT / 32; ++i2) s2 += red[i2];
            g_corr[cid] = s2;
        }
    }

    // ================= common epilogue: last block finalizes =================
    if (tid == 0) {
        __threadfence();
        int v = atomicAdd(&g_done, 1);
        last_flag = (v == NTOT - 1);
    }
    __syncthreads();

    if (last_flag) {
        __threadfence();
        float s = 0.f;
        for (int k = tid; k < NMAIN; k += NT) s += 2.0f * __ldcg(&g_partials[k]);
        for (int k = tid; k < NCORRB; k += NT) s += __ldcg(&g_corr[k]);
        #pragma unroll
        for (int o = 16; o > 0; o >>= 1)
            s += __shfl_xor_sync(0xffffffffu, s, o);
        if (px == 0) red[ty] = s;
        __syncthreads();
        if (tid == 0) {
            float t = 0.f;
            #pragma unroll
            for (int i = 0; i < NT / 32; ++i) t += red[i];
            // mean over 16 * 246 * 246 * 120 = 116,190,720 entries
            out[0] = t * (1.0f / 116190720.0f);
            g_done = 0;   // reset for graph replay
        }
    }
}

extern "C" void kernel_launch(void* const* d_in, const int* in_sizes, int n_in,
                              void* d_out, int out_size) {
    const float* orig = (const float*)d_in[0];
    const float* sim  = (const float*)d_in[1];
    float* out = (float*)d_out;

    contrast_loss_kernel<<<NTOT, NT>>>(orig, sim, out);
}